// round 10
// baseline (speedup 1.0000x reference)
#include <cuda_runtime.h>
#include <cuda_bf16.h>
#include <math.h>
#include <stdint.h>

#define NB   64
#define NPER 256
#define DIN  256
#define DOUT 128
#define EPER 8192
#define MAXE 192
#define ADJ_N 8192
#define ADJ_ELEMS (67108864u)
#define NROWS (NB*NPER)          // 16384

// ---------------- scratch ----------------
__device__ float g_T[NROWS*512];                // X @ Wcat  (cols: Wf_top|Wf_bot|Wp_top|Wp_bot)
__device__ float g_feat[NROWS*DOUT];
__device__ float g_assign[NROWS*DOUT];
__device__ float g_AS[NROWS*DOUT];
__device__ unsigned char g_elist[NROWS*MAXE];
__device__ int   g_ecnt[NROWS];
__device__ float g_ideg[NROWS];
// fragment-major bf16x2 words
__device__ unsigned int g_Xh[NROWS*128];
__device__ unsigned int g_Xl[NROWS*128];
__device__ unsigned int g_WTh[512*128];
__device__ unsigned int g_WTl[512*128];

// ---------------- f32x2 helpers ----------------
__device__ __forceinline__ unsigned long long fma2(unsigned long long a,
                                                   unsigned long long b,
                                                   unsigned long long c) {
    unsigned long long d;
    asm("fma.rn.f32x2 %0, %1, %2, %3;" : "=l"(d) : "l"(a), "l"(b), "l"(c));
    return d;
}
__device__ __forceinline__ unsigned long long add2(unsigned long long a,
                                                   unsigned long long b) {
    unsigned long long d;
    asm("add.rn.f32x2 %0, %1, %2;" : "=l"(d) : "l"(a), "l"(b));
    return d;
}
__device__ __forceinline__ unsigned long long dup2(float w) {
    unsigned long long d;
    asm("mov.b64 %0, {%1, %1};" : "=l"(d) : "f"(w));
    return d;
}
__device__ __forceinline__ void unpack2(unsigned long long v, float& lo, float& hi) {
    asm("mov.b64 {%0, %1}, %2;" : "=f"(lo), "=f"(hi) : "l"(v));
}

// ---------------- mma.sync bf16 ----------
__device__ __forceinline__ void mma16816(float* c, const uint32_t* a, const uint32_t* b) {
    asm volatile(
        "mma.sync.aligned.m16n8k16.row.col.f32.bf16.bf16.f32 "
        "{%0,%1,%2,%3}, {%4,%5,%6,%7}, {%8,%9}, {%0,%1,%2,%3};"
        : "+f"(c[0]), "+f"(c[1]), "+f"(c[2]), "+f"(c[3])
        : "r"(a[0]), "r"(a[1]), "r"(a[2]), "r"(a[3]), "r"(b[0]), "r"(b[1]));
}

// ---------------- K-build ----------------
__global__ void k_build(const int* __restrict__ esrc, const int* __restrict__ edst) {
    int b = blockIdx.x;
    __shared__ int scnt[NPER];
    for (int i = threadIdx.x; i < NPER; i += blockDim.x) scnt[i] = 0;
    __syncthreads();
    const int* s = esrc + b*EPER;
    const int* d = edst + b*EPER;
    for (int e = threadIdx.x; e < EPER; e += blockDim.x) {
        int dst = d[e];
        int src = s[e];
        int pos = atomicAdd(&scnt[dst], 1);
        if (pos < MAXE) g_elist[(b*NPER + dst)*MAXE + pos] = (unsigned char)src;
    }
    __syncthreads();
    for (int i = threadIdx.x; i < NPER; i += blockDim.x) {
        int c = scnt[i];
        g_ecnt[b*NPER + i] = c;
        g_ideg[b*NPER + i] = 1.0f / (float)(c > 0 ? c : 1);
    }
}

// ---------------- K-prep ----------------
__device__ __forceinline__ void split2(float a, float b, unsigned int& hi, unsigned int& lo) {
    __nv_bfloat16 ah = __float2bfloat16(a);
    __nv_bfloat16 bh = __float2bfloat16(b);
    __nv_bfloat16 al = __float2bfloat16(a - __bfloat162float(ah));
    __nv_bfloat16 bl = __float2bfloat16(b - __bfloat162float(bh));
    __nv_bfloat162 hh; hh.x = ah; hh.y = bh;
    __nv_bfloat162 ll; ll.x = al; ll.y = bl;
    hi = *reinterpret_cast<unsigned int*>(&hh);
    lo = *reinterpret_cast<unsigned int*>(&ll);
}

__global__ void __launch_bounds__(256) k_prep(
        const float* __restrict__ h,
        const float* __restrict__ Wf, const float* __restrict__ Wp) {
    __shared__ float hs[16*256];
    int t = threadIdx.x;
    if (blockIdx.x < 1024) {
        int mt = blockIdx.x;
        const float4* src = (const float4*)(h + (size_t)mt*16*DIN);
        #pragma unroll
        for (int k = 0; k < 4; k++)
            ((float4*)hs)[t + k*256] = src[t + k*256];
        __syncthreads();
        #pragma unroll
        for (int k = 0; k < 8; k++) {
            int w = t + k*256;
            int reg = w & 3, lane = (w >> 2) & 31, kc = w >> 7;
            int g = lane >> 2, tg = lane & 3;
            int row = g + (reg & 1)*8;
            int wc = tg + (reg >> 1)*4;
            const float* hp = hs + row*256 + (kc*8 + wc)*2;
            unsigned int hi, lo;
            split2(hp[0], hp[1], hi, lo);
            g_Xh[(size_t)mt*2048 + w] = hi;
            g_Xl[(size_t)mt*2048 + w] = lo;
        }
    } else {
        int widx = (blockIdx.x - 1024)*256 + t;
        int reg = widx & 1, lane = (widx >> 1) & 31, kc = (widx >> 6) & 15, nt = widx >> 10;
        int g = lane >> 2, tg = lane & 3;
        int n = nt*8 + g;
        int w = tg + reg*4;
        int k = (kc*8 + w)*2;
        int seg = n >> 7;
        const float* Wb = (seg < 2) ? Wf : Wp;
        int col = n & 127;
        int krow = k + ((seg & 1) ? 256 : 0);
        float x0 = Wb[(size_t)krow*128 + col];
        float x1 = Wb[(size_t)(krow+1)*128 + col];
        unsigned int hi, lo;
        split2(x0, x1, hi, lo);
        g_WTh[widx] = hi;
        g_WTl[widx] = lo;
    }
}

// ---------------- K-gemm (HMMA) ----------------
__global__ void __launch_bounds__(256) k_gemm_mma() {
    int t = threadIdx.x, lane = t & 31, w = t >> 5;
    int wm = w & 1, wn = w >> 1;
    int mt0 = blockIdx.x*8 + wm*4;
    int nt0 = blockIdx.y*16 + wn*4;

    float acc[4][4][4];
    #pragma unroll
    for (int i = 0; i < 4; i++)
        #pragma unroll
        for (int j = 0; j < 4; j++)
            #pragma unroll
            for (int r = 0; r < 4; r++) acc[i][j][r] = 0.f;

    const uint4* Xh4 = (const uint4*)g_Xh;
    const uint4* Xl4 = (const uint4*)g_Xl;
    const uint2* Wh2 = (const uint2*)g_WTh;
    const uint2* Wl2 = (const uint2*)g_WTl;

    for (int kc = 0; kc < 16; kc++) {
        uint4 Ah[4], Al[4];
        uint2 Bh[4], Bl[4];
        #pragma unroll
        for (int i = 0; i < 4; i++) {
            int off = ((mt0 + i)*16 + kc)*32 + lane;
            Ah[i] = Xh4[off];
            Al[i] = Xl4[off];
        }
        #pragma unroll
        for (int j = 0; j < 4; j++) {
            int off = ((nt0 + j)*16 + kc)*32 + lane;
            Bh[j] = Wh2[off];
            Bl[j] = Wl2[off];
        }
        #pragma unroll
        for (int i = 0; i < 4; i++) {
            #pragma unroll
            for (int j = 0; j < 4; j++) {
                mma16816(acc[i][j], (const uint32_t*)&Ah[i], (const uint32_t*)&Bh[j]);
                mma16816(acc[i][j], (const uint32_t*)&Ah[i], (const uint32_t*)&Bl[j]);
                mma16816(acc[i][j], (const uint32_t*)&Al[i], (const uint32_t*)&Bh[j]);
            }
        }
    }

    int g = lane >> 2, tg = lane & 3;
    #pragma unroll
    for (int i = 0; i < 4; i++) {
        #pragma unroll
        for (int j = 0; j < 4; j++) {
            size_t row = (size_t)(mt0 + i)*16 + g;
            size_t col = (size_t)(nt0 + j)*8 + tg*2;
            *(float2*)(g_T + row*512 + col)       = make_float2(acc[i][j][0], acc[i][j][1]);
            *(float2*)(g_T + (row + 8)*512 + col) = make_float2(acc[i][j][2], acc[i][j][3]);
        }
    }
}

// ---------------- K-fuse: dst-half split ----------------
// grid (NB, 2 which, 2 dh); block 1024; smem 128KB (full T_bot tile); 4 dsts/warp
__global__ void __launch_bounds__(1024) k_fuse(const float* __restrict__ bf,
                                               const float* __restrict__ bp) {
    extern __shared__ float ts[];
    int b = blockIdx.x, which = blockIdx.y, dh = blockIdx.z, t = threadIdx.x;
    int top_off = which*256, bot_off = which*256 + 128;
    for (int i4 = t; i4 < 256*32; i4 += 1024) {
        int node = i4 >> 5, f4 = i4 & 31;
        ((float4*)ts)[i4] = *(const float4*)(g_T + (size_t)(b*NPER + node)*512 + bot_off + f4*4);
    }
    __syncthreads();
    const ulonglong2* tsv = (const ulonglong2*)ts;
    int w = t >> 5, l = t & 31;
    const float* bias = which ? bp : bf;
    float4 bias4 = *(const float4*)(bias + l*4);

    for (int ii = 0; ii < 4; ii++) {
        int dst = dh*128 + w*4 + ii;
        int gi = b*NPER + dst;
        int nn = g_ecnt[gi]; if (nn > MAXE) nn = MAXE;
        float ideg = g_ideg[gi];
        const unsigned char* lst = &g_elist[(size_t)gi*MAXE];
        unsigned long long a0 = 0, a1 = 0, b0 = 0, b1 = 0;
        int j = 0;
        for (; j + 4 <= nn; j += 4) {
            uchar4 s4 = *(const uchar4*)(lst + j);
            ulonglong2 v0 = tsv[s4.x*32 + l];
            ulonglong2 v1 = tsv[s4.y*32 + l];
            ulonglong2 v2 = tsv[s4.z*32 + l];
            ulonglong2 v3 = tsv[s4.w*32 + l];
            a0 = add2(a0, v0.x); a1 = add2(a1, v0.y);
            b0 = add2(b0, v1.x); b1 = add2(b1, v1.y);
            a0 = add2(a0, v2.x); a1 = add2(a1, v2.y);
            b0 = add2(b0, v3.x); b1 = add2(b1, v3.y);
        }
        for (; j < nn; j++) {
            ulonglong2 v = tsv[lst[j]*32 + l];
            a0 = add2(a0, v.x); a1 = add2(a1, v.y);
        }
        a0 = add2(a0, b0); a1 = add2(a1, b1);
        float s0, s1, s2, s3;
        unpack2(a0, s0, s1); unpack2(a1, s2, s3);

        float4 top = *(const float4*)(g_T + (size_t)gi*512 + top_off + l*4);
        float z0 = fmaf(ideg, s0, top.x) + bias4.x;
        float z1 = fmaf(ideg, s1, top.y) + bias4.y;
        float z2 = fmaf(ideg, s2, top.z) + bias4.z;
        float z3 = fmaf(ideg, s3, top.w) + bias4.w;

        float ss = z0*z0 + z1*z1 + z2*z2 + z3*z3;
        #pragma unroll
        for (int o = 16; o > 0; o >>= 1) ss += __shfl_xor_sync(0xffffffffu, ss, o);
        float inv = rsqrtf(fmaxf(ss, 1e-24f));
        z0 = fmaxf(z0*inv, 0.f); z1 = fmaxf(z1*inv, 0.f);
        z2 = fmaxf(z2*inv, 0.f); z3 = fmaxf(z3*inv, 0.f);

        if (which == 0) {
            *(float4*)(g_feat + (size_t)gi*DOUT + l*4) = make_float4(z0, z1, z2, z3);
        } else {
            float m = fmaxf(fmaxf(z0, z1), fmaxf(z2, z3));
            #pragma unroll
            for (int o = 16; o > 0; o >>= 1) m = fmaxf(m, __shfl_xor_sync(0xffffffffu, m, o));
            float e0 = __expf(z0 - m), e1 = __expf(z1 - m);
            float e2 = __expf(z2 - m), e3 = __expf(z3 - m);
            float s = e0 + e1 + e2 + e3;
            #pragma unroll
            for (int o = 16; o > 0; o >>= 1) s += __shfl_xor_sync(0xffffffffu, s, o);
            float isum = 1.0f / s;
            *(float4*)(g_assign + (size_t)gi*DOUT + l*4) =
                make_float4(e0*isum, e1*isum, e2*isum, e3*isum);
        }
    }
}

// ---------------- K-as: dst-quarter split ----------------
// grid (NB, 4 dq); block 1024; smem 128KB; 2 dsts/warp
__global__ void __launch_bounds__(1024) k_as() {
    extern __shared__ float ss[];
    int b = blockIdx.x, dq = blockIdx.y, t = threadIdx.x;
    const float4* Sg4 = (const float4*)(g_assign + (size_t)b*NPER*DOUT);
    for (int i4 = t; i4 < 256*32; i4 += 1024) ((float4*)ss)[i4] = Sg4[i4];
    __syncthreads();
    const ulonglong2* ssv = (const ulonglong2*)ss;
    int w = t >> 5, l = t & 31;
    for (int ii = 0; ii < 2; ii++) {
        int dst = dq*64 + w*2 + ii;
        int gi = b*NPER + dst;
        int nn = g_ecnt[gi]; if (nn > MAXE) nn = MAXE;
        const unsigned char* lst = &g_elist[(size_t)gi*MAXE];
        unsigned long long a0 = 0, a1 = 0, b0 = 0, b1 = 0;
        int j = 0;
        for (; j + 4 <= nn; j += 4) {
            uchar4 s4 = *(const uchar4*)(lst + j);
            ulonglong2 v0 = ssv[s4.x*32 + l];
            ulonglong2 v1 = ssv[s4.y*32 + l];
            ulonglong2 v2 = ssv[s4.z*32 + l];
            ulonglong2 v3 = ssv[s4.w*32 + l];
            a0 = add2(a0, v0.x); a1 = add2(a1, v0.y);
            b0 = add2(b0, v1.x); b1 = add2(b1, v1.y);
            a0 = add2(a0, v2.x); a1 = add2(a1, v2.y);
            b0 = add2(b0, v3.x); b1 = add2(b1, v3.y);
        }
        for (; j < nn; j++) {
            ulonglong2 v = ssv[lst[j]*32 + l];
            a0 = add2(a0, v.x); a1 = add2(a1, v.y);
        }
        a0 = add2(a0, b0); a1 = add2(a1, b1);
        float x0, x1, x2, x3;
        unpack2(a0, x0, x1); unpack2(a1, x2, x3);
        *(float4*)(g_AS + (size_t)gi*DOUT + l*4) = make_float4(x0, x1, x2, x3);
    }
}

// ---------------- K-pool: out = S^T @ X ; column-half split ----------------
// grid (NB, 2 which, 2 ch); block 256; smem 48KB (S 64x128 + X 64x64)
// thread = 8 out-rows (tk) x 4 out-cols (td); out tile 128 x 64
__global__ void __launch_bounds__(256) k_pool(float* __restrict__ out) {
    extern __shared__ float sm[];
    float* Ssm = sm;            // 64 x 128
    float* Xsm = sm + 8192;     // 64 x 64
    int b = blockIdx.x, which = blockIdx.y, ch = blockIdx.z;
    int t = threadIdx.x;
    int tk = t >> 4, td = t & 15;

    const float* Sg = g_assign + (size_t)b*NPER*DOUT;
    const float* Xg = (which ? g_AS : g_feat) + (size_t)b*NPER*DOUT + ch*64;

    unsigned long long acc[8][2];
    #pragma unroll
    for (int i = 0; i < 8; i++) { acc[i][0] = 0ull; acc[i][1] = 0ull; }

    for (int c = 0; c < NPER; c += 64) {
        const float4* Sg4 = (const float4*)(Sg + c*128);
        for (int i4 = t; i4 < 64*32; i4 += 256) ((float4*)Ssm)[i4] = Sg4[i4];
        for (int i4 = t; i4 < 64*16; i4 += 256) {
            int n = i4 >> 4, f4 = i4 & 15;
            ((float4*)Xsm)[i4] = *(const float4*)(Xg + (size_t)(c + n)*128 + f4*4);
        }
        __syncthreads();
        for (int n = 0; n < 64; n++) {
            float4 a0 = ((const float4*)(Ssm + n*128))[tk*2];
            float4 a1 = ((const float4*)(Ssm + n*128))[tk*2 + 1];
            ulonglong2 x = ((const ulonglong2*)(Xsm + n*64))[td];
            unsigned long long A[8] = {
                dup2(a0.x), dup2(a0.y), dup2(a0.z), dup2(a0.w),
                dup2(a1.x), dup2(a1.y), dup2(a1.z), dup2(a1.w)
            };
            #pragma unroll
            for (int i = 0; i < 8; i++) {
                acc[i][0] = fma2(x.x, A[i], acc[i][0]);
                acc[i][1] = fma2(x.y, A[i], acc[i][1]);
            }
        }
        __syncthreads();
    }

    #pragma unroll
    for (int i = 0; i < 8; i++) {
        size_t grow = (size_t)b*128 + tk*8 + i;
        size_t base = which ? (grow*ADJ_N + (size_t)b*128 + ch*64 + td*4)
                            : ((size_t)ADJ_ELEMS + grow*DOUT + ch*64 + td*4);
        float lo0, hi0, lo1, hi1;
        unpack2(acc[i][0], lo0, hi0);
        unpack2(acc[i][1], lo1, hi1);
        *(float4*)(out + base) = make_float4(lo0, hi0, lo1, hi1);
    }
}

// ---------------- launch ----------------
extern "C" void kernel_launch(void* const* d_in, const int* in_sizes, int n_in,
                              void* d_out, int out_size) {
    const float* h    = (const float*)d_in[0];
    const int*   esrc = (const int*)d_in[1];
    const int*   edst = (const int*)d_in[2];
    const float* Wf   = (const float*)d_in[3];
    const float* bf   = (const float*)d_in[4];
    const float* Wp   = (const float*)d_in[5];
    const float* bp   = (const float*)d_in[6];
    float* out = (float*)d_out;

    static cudaStream_t s_side = nullptr;
    static cudaEvent_t  e_fork = nullptr, e_build = nullptr, e_join = nullptr;
    static bool attr_done = false;
    if (!s_side) {
        cudaStreamCreateWithFlags(&s_side, cudaStreamNonBlocking);
        cudaEventCreateWithFlags(&e_fork,  cudaEventDisableTiming);
        cudaEventCreateWithFlags(&e_build, cudaEventDisableTiming);
        cudaEventCreateWithFlags(&e_join,  cudaEventDisableTiming);
    }
    if (!attr_done) {
        cudaFuncSetAttribute(k_fuse, cudaFuncAttributeMaxDynamicSharedMemorySize, 131072);
        cudaFuncSetAttribute(k_as,   cudaFuncAttributeMaxDynamicSharedMemorySize, 131072);
        cudaFuncSetAttribute(k_pool, cudaFuncAttributeMaxDynamicSharedMemorySize, 49152);
        attr_done = true;
    }

    // side stream: edge-list build, then adj memset (overlaps prep+gemm)
    cudaEventRecord(e_fork, 0);
    cudaStreamWaitEvent(s_side, e_fork, 0);
    k_build<<<NB, 256, 0, s_side>>>(esrc, edst);
    cudaEventRecord(e_build, s_side);
    cudaMemsetAsync(d_out, 0, (size_t)ADJ_ELEMS * sizeof(float), s_side);
    cudaEventRecord(e_join, s_side);

    // main stream
    k_prep<<<1280, 256>>>(h, Wf, Wp);
    k_gemm_mma<<<dim3(128, 4), 256>>>();
    cudaStreamWaitEvent(0, e_build, 0);
    k_fuse<<<dim3(NB, 2, 2), 1024, 131072>>>(bf, bp);
    k_as<<<dim3(NB, 4), 1024, 131072>>>();
    cudaStreamWaitEvent(0, e_join, 0);
    k_pool<<<dim3(NB, 2, 2), 256, 49152>>>(out);
}

// round 11
// speedup vs baseline: 1.0008x; 1.0008x over previous
#include <cuda_runtime.h>
#include <cuda_bf16.h>
#include <math.h>
#include <stdint.h>

#define NB   64
#define NPER 256
#define DIN  256
#define DOUT 128
#define EPER 8192
#define ADJ_N 8192
#define ADJ_ELEMS (67108864u)
#define NROWS (NB*NPER)          // 16384

// ---------------- scratch ----------------
__device__ float g_T[NROWS*512];          // X @ Wcat (cols: Wf_top|Wf_bot|Wp_top|Wp_bot)
__device__ float g_A[NB*NPER*NPER];       // dense adjacency counts [b][dst][src] (fp32)
__device__ float g_AG[NB*NPER*256];       // A @ [T_fbot|T_pbot]   [b][dst][256]
__device__ float g_feat[NROWS*DOUT];
__device__ float g_assign[NROWS*DOUT];
__device__ float g_AS[NROWS*DOUT];
__device__ float g_ideg[NROWS];
// mma fragment arrays (bf16x2 words)
__device__ unsigned int g_Xh[NROWS*128];     // X hi  [mt][kc][lane][4]
__device__ unsigned int g_Xl[NROWS*128];
__device__ unsigned int g_WTh[512*128];      // Wcat^T hi [nt][kc][lane][2]
__device__ unsigned int g_WTl[512*128];
__device__ unsigned int g_Afrag[NB*16*2048]; // A (exact bf16) [b][mt][kc][lane][4]
__device__ unsigned int g_Th[NB*32768];      // T_bot hi [b][nt(32)][kc][lane][2]
__device__ unsigned int g_Tl[NB*32768];
__device__ unsigned int g_Sh[NB*16384];      // assign hi [b][nt(16)][kc][lane][2]
__device__ unsigned int g_Sl[NB*16384];

// ---------------- f32x2 helpers (k_pool) ----------------
__device__ __forceinline__ unsigned long long fma2(unsigned long long a,
                                                   unsigned long long b,
                                                   unsigned long long c) {
    unsigned long long d;
    asm("fma.rn.f32x2 %0, %1, %2, %3;" : "=l"(d) : "l"(a), "l"(b), "l"(c));
    return d;
}
__device__ __forceinline__ unsigned long long dup2(float w) {
    unsigned long long d;
    asm("mov.b64 %0, {%1, %1};" : "=l"(d) : "f"(w));
    return d;
}
__device__ __forceinline__ void unpack2(unsigned long long v, float& lo, float& hi) {
    asm("mov.b64 {%0, %1}, %2;" : "=f"(lo), "=f"(hi) : "l"(v));
}

// ---------------- mma.sync bf16 ----------
__device__ __forceinline__ void mma16816(float* c, const uint32_t* a, const uint32_t* b) {
    asm volatile(
        "mma.sync.aligned.m16n8k16.row.col.f32.bf16.bf16.f32 "
        "{%0,%1,%2,%3}, {%4,%5,%6,%7}, {%8,%9}, {%0,%1,%2,%3};"
        : "+f"(c[0]), "+f"(c[1]), "+f"(c[2]), "+f"(c[3])
        : "r"(a[0]), "r"(a[1]), "r"(a[2]), "r"(a[3]), "r"(b[0]), "r"(b[1]));
}

__device__ __forceinline__ void split2(float a, float b, unsigned int& hi, unsigned int& lo) {
    __nv_bfloat16 ah = __float2bfloat16(a);
    __nv_bfloat16 bh = __float2bfloat16(b);
    __nv_bfloat16 al = __float2bfloat16(a - __bfloat162float(ah));
    __nv_bfloat16 bl = __float2bfloat16(b - __bfloat162float(bh));
    __nv_bfloat162 hh; hh.x = ah; hh.y = bh;
    __nv_bfloat162 ll; ll.x = al; ll.y = bl;
    hi = *reinterpret_cast<unsigned int*>(&hh);
    lo = *reinterpret_cast<unsigned int*>(&ll);
}

// ---------------- K-buildA: zero + scatter dense adjacency, degrees ----------
__global__ void k_buildA(const int* __restrict__ esrc, const int* __restrict__ edst) {
    int b = blockIdx.x, t = threadIdx.x;
    float* A = g_A + (size_t)b*65536;
    float4* A4 = (float4*)A;
    for (int i = t; i < 16384; i += 256) A4[i] = make_float4(0.f, 0.f, 0.f, 0.f);
    __shared__ int scnt[NPER];
    if (t < 256) scnt[t] = 0;
    __syncthreads();
    const int* s = esrc + b*EPER;
    const int* d = edst + b*EPER;
    for (int e = t; e < EPER; e += 256) {
        int dst = d[e], src = s[e];
        atomicAdd(&scnt[dst], 1);
        atomicAdd(&A[dst*256 + src], 1.0f);
    }
    __syncthreads();
    if (t < 256) {
        int c = scnt[t];
        g_ideg[b*NPER + t] = 1.0f / (float)(c > 0 ? c : 1);
    }
}

// ---------------- K-prep: X/W bf16 hi/lo fragments (unchanged R9) ----------
__global__ void __launch_bounds__(256) k_prep(
        const float* __restrict__ h,
        const float* __restrict__ Wf, const float* __restrict__ Wp) {
    __shared__ float hs[16*256];
    int t = threadIdx.x;
    if (blockIdx.x < 1024) {
        int mt = blockIdx.x;
        const float4* src = (const float4*)(h + (size_t)mt*16*DIN);
        #pragma unroll
        for (int k = 0; k < 4; k++)
            ((float4*)hs)[t + k*256] = src[t + k*256];
        __syncthreads();
        #pragma unroll
        for (int k = 0; k < 8; k++) {
            int w = t + k*256;
            int reg = w & 3, lane = (w >> 2) & 31, kc = w >> 7;
            int g = lane >> 2, tg = lane & 3;
            int row = g + (reg & 1)*8;
            int wc = tg + (reg >> 1)*4;
            const float* hp = hs + row*256 + (kc*8 + wc)*2;
            unsigned int hi, lo;
            split2(hp[0], hp[1], hi, lo);
            g_Xh[(size_t)mt*2048 + w] = hi;
            g_Xl[(size_t)mt*2048 + w] = lo;
        }
    } else {
        int widx = (blockIdx.x - 1024)*256 + t;
        int reg = widx & 1, lane = (widx >> 1) & 31, kc = (widx >> 6) & 15, nt = widx >> 10;
        int g = lane >> 2, tg = lane & 3;
        int n = nt*8 + g;
        int w = tg + reg*4;
        int k = (kc*8 + w)*2;
        int seg = n >> 7;
        const float* Wb = (seg < 2) ? Wf : Wp;
        int col = n & 127;
        int krow = k + ((seg & 1) ? 256 : 0);
        float x0 = Wb[(size_t)krow*128 + col];
        float x1 = Wb[(size_t)(krow+1)*128 + col];
        unsigned int hi, lo;
        split2(x0, x1, hi, lo);
        g_WTh[widx] = hi;
        g_WTl[widx] = lo;
    }
}

// ---------------- K-gemm (HMMA): T = X @ Wcat, 3-pass split ----------------
__global__ void __launch_bounds__(256) k_gemm_mma() {
    int t = threadIdx.x, lane = t & 31, w = t >> 5;
    int wm = w & 1, wn = w >> 1;
    int mt0 = blockIdx.x*8 + wm*4;
    int nt0 = blockIdx.y*16 + wn*4;

    float acc[4][4][4];
    #pragma unroll
    for (int i = 0; i < 4; i++)
        #pragma unroll
        for (int j = 0; j < 4; j++)
            #pragma unroll
            for (int r = 0; r < 4; r++) acc[i][j][r] = 0.f;

    const uint4* Xh4 = (const uint4*)g_Xh;
    const uint4* Xl4 = (const uint4*)g_Xl;
    const uint2* Wh2 = (const uint2*)g_WTh;
    const uint2* Wl2 = (const uint2*)g_WTl;

    for (int kc = 0; kc < 16; kc++) {
        uint4 Ah[4], Al[4];
        uint2 Bh[4], Bl[4];
        #pragma unroll
        for (int i = 0; i < 4; i++) {
            int off = ((mt0 + i)*16 + kc)*32 + lane;
            Ah[i] = Xh4[off];
            Al[i] = Xl4[off];
        }
        #pragma unroll
        for (int j = 0; j < 4; j++) {
            int off = ((nt0 + j)*16 + kc)*32 + lane;
            Bh[j] = Wh2[off];
            Bl[j] = Wl2[off];
        }
        #pragma unroll
        for (int i = 0; i < 4; i++) {
            #pragma unroll
            for (int j = 0; j < 4; j++) {
                mma16816(acc[i][j], (const uint32_t*)&Ah[i], (const uint32_t*)&Bh[j]);
                mma16816(acc[i][j], (const uint32_t*)&Ah[i], (const uint32_t*)&Bl[j]);
                mma16816(acc[i][j], (const uint32_t*)&Al[i], (const uint32_t*)&Bh[j]);
            }
        }
    }

    int g = lane >> 2, tg = lane & 3;
    #pragma unroll
    for (int i = 0; i < 4; i++) {
        #pragma unroll
        for (int j = 0; j < 4; j++) {
            size_t row = (size_t)(mt0 + i)*16 + g;
            size_t col = (size_t)(nt0 + j)*8 + tg*2;
            *(float2*)(g_T + row*512 + col)       = make_float2(acc[i][j][0], acc[i][j][1]);
            *(float2*)(g_T + (row + 8)*512 + col) = make_float2(acc[i][j][2], acc[i][j][3]);
        }
    }
}

// ---------------- K-prepAT: A fragments (exact) + T_bot fragments (hi/lo) -----
__global__ void __launch_bounds__(256) k_prepAT() {
    __shared__ float sm[16*256];
    int t = threadIdx.x;
    if (blockIdx.x < 1024) {
        int b = blockIdx.x >> 4, mt = blockIdx.x & 15;
        const float4* src = (const float4*)(g_A + ((size_t)b*256 + mt*16)*256);
        #pragma unroll
        for (int k = 0; k < 4; k++) ((float4*)sm)[t + k*256] = src[t + k*256];
        __syncthreads();
        #pragma unroll
        for (int k = 0; k < 8; k++) {
            int w = t + k*256;
            int reg = w & 3, lane = (w >> 2) & 31, kc = w >> 7;
            int g = lane >> 2, tg = lane & 3;
            int row = g + (reg & 1)*8;
            int col = kc*16 + tg*2 + (reg >> 1)*8;
            __nv_bfloat162 p;
            p.x = __float2bfloat16(sm[row*256 + col]);
            p.y = __float2bfloat16(sm[row*256 + col + 1]);
            g_Afrag[(size_t)(b*16 + mt)*2048 + w] = *reinterpret_cast<unsigned int*>(&p);
        }
    } else {
        int q = blockIdx.x - 1024;
        int b = q >> 4, kc = q & 15;
        // load T_bot both whiches: smem col cc<128 <-> T col 128+cc ; cc>=128 <-> 256+cc
        #pragma unroll
        for (int k = 0; k < 4; k++) {
            int idx4 = t + k*256;
            int r = idx4 >> 6, cc4 = idx4 & 63;
            int tcol4 = (cc4 < 32) ? (32 + cc4) : (64 + cc4);
            ((float4*)sm)[idx4] =
                *(const float4*)(g_T + (size_t)(b*256 + kc*16 + r)*512 + tcol4*4);
        }
        __syncthreads();
        #pragma unroll
        for (int k = 0; k < 8; k++) {
            int w = t + k*256;   // 2048 words
            int reg = w & 1, lane = (w >> 1) & 31, nt = w >> 6;
            int g = lane >> 2, tg = lane & 3;
            int n = nt*8 + g;
            int k0 = tg*2 + reg*8;
            unsigned int hi, lo;
            split2(sm[k0*256 + n], sm[(k0+1)*256 + n], hi, lo);
            size_t idx = (size_t)b*32768 + nt*1024 + kc*64 + (w & 63);
            g_Th[idx] = hi;
            g_Tl[idx] = lo;
        }
    }
}

// ---------------- K-agg2: AG = A @ [T_fbot|T_pbot]  (2-pass) -------------------
// grid (NB, 2 mh, 2 nh); block 256 = 8 warps (wm 2 x wn 4); warp 4mt x 4nt
__global__ void __launch_bounds__(256) k_agg2() {
    int t = threadIdx.x, lane = t & 31, w = t >> 5;
    int b = blockIdx.x, mh = blockIdx.y, nh = blockIdx.z;
    int wm = w & 1, wn = w >> 1;
    int mt0 = mh*8 + wm*4;
    int nt0 = nh*16 + wn*4;

    float acc[4][4][4];
    #pragma unroll
    for (int i = 0; i < 4; i++)
        #pragma unroll
        for (int j = 0; j < 4; j++)
            #pragma unroll
            for (int r = 0; r < 4; r++) acc[i][j][r] = 0.f;

    const uint4* A4 = (const uint4*)g_Afrag;
    const uint2* Bh2 = (const uint2*)g_Th;
    const uint2* Bl2 = (const uint2*)g_Tl;

    for (int kc = 0; kc < 16; kc++) {
        uint4 Af[4];
        uint2 Bh[4], Bl[4];
        #pragma unroll
        for (int i = 0; i < 4; i++)
            Af[i] = A4[(size_t)(b*16 + mt0 + i)*512 + kc*32 + lane];
        #pragma unroll
        for (int j = 0; j < 4; j++) {
            size_t o = (size_t)b*16384 + (nt0 + j)*512 + kc*32 + lane;
            Bh[j] = Bh2[o];
            Bl[j] = Bl2[o];
        }
        #pragma unroll
        for (int i = 0; i < 4; i++) {
            #pragma unroll
            for (int j = 0; j < 4; j++) {
                mma16816(acc[i][j], (const uint32_t*)&Af[i], (const uint32_t*)&Bh[j]);
                mma16816(acc[i][j], (const uint32_t*)&Af[i], (const uint32_t*)&Bl[j]);
            }
        }
    }

    int g = lane >> 2, tg = lane & 3;
    #pragma unroll
    for (int i = 0; i < 4; i++) {
        #pragma unroll
        for (int j = 0; j < 4; j++) {
            size_t row = (size_t)(mt0 + i)*16 + g;
            size_t col = (size_t)(nt0 + j)*8 + tg*2;
            *(float2*)(g_AG + ((size_t)b*256 + row)*256 + col)     = make_float2(acc[i][j][0], acc[i][j][1]);
            *(float2*)(g_AG + ((size_t)b*256 + row + 8)*256 + col) = make_float2(acc[i][j][2], acc[i][j][3]);
        }
    }
}

// ---------------- K-epi: z = T_top + ideg*AG + bias; norm/relu/softmax --------
// grid 1024 (b,kc); block 256 = 8 warps x 4 tasks (16 nodes x 2 which).
// also emits assign bf16 hi/lo B-fragments for k_as2.
__global__ void __launch_bounds__(256) k_epi(const float* __restrict__ bf,
                                             const float* __restrict__ bp) {
    __shared__ float smS[16*128];   // assign staging
    int b = blockIdx.x >> 4, kc = blockIdx.x & 15;
    int t = threadIdx.x, w = t >> 5, l = t & 31;

    #pragma unroll
    for (int i = 0; i < 4; i++) {
        int task = w*4 + i;
        int which = task >> 4, nl = task & 15;
        int gi = b*256 + kc*16 + nl;
        const float* bias = which ? bp : bf;
        float4 bias4 = *(const float4*)(bias + l*4);
        float4 top = *(const float4*)(g_T + (size_t)gi*512 + which*256 + l*4);
        float4 ag  = *(const float4*)(g_AG + (size_t)gi*256 + which*128 + l*4);
        float ideg = g_ideg[gi];

        float z0 = fmaf(ideg, ag.x, top.x) + bias4.x;
        float z1 = fmaf(ideg, ag.y, top.y) + bias4.y;
        float z2 = fmaf(ideg, ag.z, top.z) + bias4.z;
        float z3 = fmaf(ideg, ag.w, top.w) + bias4.w;

        float ss = z0*z0 + z1*z1 + z2*z2 + z3*z3;
        #pragma unroll
        for (int o = 16; o > 0; o >>= 1) ss += __shfl_xor_sync(0xffffffffu, ss, o);
        float inv = rsqrtf(fmaxf(ss, 1e-24f));
        z0 = fmaxf(z0*inv, 0.f); z1 = fmaxf(z1*inv, 0.f);
        z2 = fmaxf(z2*inv, 0.f); z3 = fmaxf(z3*inv, 0.f);

        if (which == 0) {
            *(float4*)(g_feat + (size_t)gi*DOUT + l*4) = make_float4(z0, z1, z2, z3);
        } else {
            float m = fmaxf(fmaxf(z0, z1), fmaxf(z2, z3));
            #pragma unroll
            for (int o = 16; o > 0; o >>= 1) m = fmaxf(m, __shfl_xor_sync(0xffffffffu, m, o));
            float e0 = __expf(z0 - m), e1 = __expf(z1 - m);
            float e2 = __expf(z2 - m), e3 = __expf(z3 - m);
            float s = (e0 + e1) + (e2 + e3);
            #pragma unroll
            for (int o = 16; o > 0; o >>= 1) s += __shfl_xor_sync(0xffffffffu, s, o);
            float isum = 1.0f / s;
            float a0 = e0*isum, a1 = e1*isum, a2 = e2*isum, a3 = e3*isum;
            *(float4*)(g_assign + (size_t)gi*DOUT + l*4) = make_float4(a0, a1, a2, a3);
            smS[nl*128 + l*4 + 0] = a0;
            smS[nl*128 + l*4 + 1] = a1;
            smS[nl*128 + l*4 + 2] = a2;
            smS[nl*128 + l*4 + 3] = a3;
        }
    }
    __syncthreads();

    // emit assign B-fragments (hi/lo) for this (b,kc): 1024 words each
    #pragma unroll
    for (int k = 0; k < 4; k++) {
        int w2 = t + k*256;
        int reg = w2 & 1, lane = (w2 >> 1) & 31, nt = w2 >> 6;
        int g = lane >> 2, tg = lane & 3;
        int n = nt*8 + g;
        int k0 = tg*2 + reg*8;
        unsigned int hi, lo;
        split2(smS[k0*128 + n], smS[(k0+1)*128 + n], hi, lo);
        size_t idx = (size_t)b*16384 + nt*1024 + kc*64 + (w2 & 63);
        g_Sh[idx] = hi;
        g_Sl[idx] = lo;
    }
}

// ---------------- K-as2: AS = A @ assign (2-pass) ------------------------------
// grid (NB, 2 mh); block 256 = 8 warps; warp 4mt x 4nt (N=128 -> 16 nt)
__global__ void __launch_bounds__(256) k_as2() {
    int t = threadIdx.x, lane = t & 31, w = t >> 5;
    int b = blockIdx.x;
    int wm = w & 1, wn = w >> 1;
    int mt0 = blockIdx.y*8 + wm*4;
    int nt0 = wn*4;

    float acc[4][4][4];
    #pragma unroll
    for (int i = 0; i < 4; i++)
        #pragma unroll
        for (int j = 0; j < 4; j++)
            #pragma unroll
            for (int r = 0; r < 4; r++) acc[i][j][r] = 0.f;

    const uint4* A4 = (const uint4*)g_Afrag;
    const uint2* Bh2 = (const uint2*)g_Sh;
    const uint2* Bl2 = (const uint2*)g_Sl;

    for (int kc = 0; kc < 16; kc++) {
        uint4 Af[4];
        uint2 Bh[4], Bl[4];
        #pragma unroll
        for (int i = 0; i < 4; i++)
            Af[i] = A4[(size_t)(b*16 + mt0 + i)*512 + kc*32 + lane];
        #pragma unroll
        for (int j = 0; j < 4; j++) {
            size_t o = (size_t)b*8192 + (nt0 + j)*512 + kc*32 + lane;
            Bh[j] = Bh2[o];
            Bl[j] = Bl2[o];
        }
        #pragma unroll
        for (int i = 0; i < 4; i++) {
            #pragma unroll
            for (int j = 0; j < 4; j++) {
                mma16816(acc[i][j], (const uint32_t*)&Af[i], (const uint32_t*)&Bh[j]);
                mma16816(acc[i][j], (const uint32_t*)&Af[i], (const uint32_t*)&Bl[j]);
            }
        }
    }

    int g = lane >> 2, tg = lane & 3;
    #pragma unroll
    for (int i = 0; i < 4; i++) {
        #pragma unroll
        for (int j = 0; j < 4; j++) {
            size_t row = (size_t)(mt0 + i)*16 + g;
            size_t col = (size_t)(nt0 + j)*8 + tg*2;
            *(float2*)(g_AS + ((size_t)b*256 + row)*128 + col)     = make_float2(acc[i][j][0], acc[i][j][1]);
            *(float2*)(g_AS + ((size_t)b*256 + row + 8)*128 + col) = make_float2(acc[i][j][2], acc[i][j][3]);
        }
    }
}

// ---------------- K-pool: out = S^T @ X (R7 team version) ---------------------
__global__ void __launch_bounds__(512) k_pool(float* __restrict__ out) {
    extern __shared__ float sm[];
    int b = blockIdx.x, which = blockIdx.y;
    int t = threadIdx.x;
    int team = t >> 8;
    int tt = t & 255;
    int tk = tt >> 4, td = tt & 15;

    float* Ssm = sm + team*16384;
    float* Xsm = sm + team*16384 + 8192;

    const float* Sg = g_assign + (size_t)b*NPER*DOUT;
    const float* Xg = (which ? g_AS : g_feat) + (size_t)b*NPER*DOUT;

    unsigned long long acc[8][4];
    #pragma unroll
    for (int i = 0; i < 8; i++)
        #pragma unroll
        for (int j = 0; j < 4; j++) acc[i][j] = 0ull;

    for (int ci = 0; ci < 2; ci++) {
        int c = team*128 + ci*64;
        const float4* Sg4 = (const float4*)(Sg + c*128);
        const float4* Xg4 = (const float4*)(Xg + c*128);
        for (int i4 = tt; i4 < 64*32; i4 += 256) {
            ((float4*)Ssm)[i4] = Sg4[i4];
            ((float4*)Xsm)[i4] = Xg4[i4];
        }
        __syncthreads();
        for (int n = 0; n < 64; n++) {
            float4 a0 = ((const float4*)(Ssm + n*128))[tk*2];
            float4 a1 = ((const float4*)(Ssm + n*128))[tk*2 + 1];
            ulonglong2 x0 = ((const ulonglong2*)(Xsm + n*128))[td*2];
            ulonglong2 x1 = ((const ulonglong2*)(Xsm + n*128))[td*2 + 1];
            unsigned long long A[8] = {
                dup2(a0.x), dup2(a0.y), dup2(a0.z), dup2(a0.w),
                dup2(a1.x), dup2(a1.y), dup2(a1.z), dup2(a1.w)
            };
            #pragma unroll
            for (int i = 0; i < 8; i++) {
                acc[i][0] = fma2(x0.x, A[i], acc[i][0]);
                acc[i][1] = fma2(x0.y, A[i], acc[i][1]);
                acc[i][2] = fma2(x1.x, A[i], acc[i][2]);
                acc[i][3] = fma2(x1.y, A[i], acc[i][3]);
            }
        }
        __syncthreads();
    }

    float* cb = sm + 16384;
    if (team == 1) {
        #pragma unroll
        for (int i = 0; i < 8; i++) {
            float* row = cb + (tk*8 + i)*128 + td*8;
            #pragma unroll
            for (int j = 0; j < 4; j++) {
                float lo, hi;
                unpack2(acc[i][j], lo, hi);
                row[2*j] = lo; row[2*j + 1] = hi;
            }
        }
    }
    __syncthreads();
    if (team == 0) {
        #pragma unroll
        for (int i = 0; i < 8; i++) {
            const float* row = cb + (tk*8 + i)*128 + td*8;
            size_t grow = (size_t)b*128 + tk*8 + i;
            size_t base = which ? (grow*ADJ_N + (size_t)b*128 + td*8)
                                : ((size_t)ADJ_ELEMS + grow*DOUT + td*8);
            #pragma unroll
            for (int j = 0; j < 4; j++) {
                float lo, hi;
                unpack2(acc[i][j], lo, hi);
                out[base + 2*j]     = lo + row[2*j];
                out[base + 2*j + 1] = hi + row[2*j + 1];
            }
        }
    }
}

// ---------------- launch ----------------
extern "C" void kernel_launch(void* const* d_in, const int* in_sizes, int n_in,
                              void* d_out, int out_size) {
    const float* h    = (const float*)d_in[0];
    const int*   esrc = (const int*)d_in[1];
    const int*   edst = (const int*)d_in[2];
    const float* Wf   = (const float*)d_in[3];
    const float* bf   = (const float*)d_in[4];
    const float* Wp   = (const float*)d_in[5];
    const float* bp   = (const float*)d_in[6];
    float* out = (float*)d_out;

    static cudaStream_t s_side = nullptr;
    static cudaEvent_t  e_fork = nullptr, e_build = nullptr, e_join = nullptr;
    static bool attr_done = false;
    if (!s_side) {
        cudaStreamCreateWithFlags(&s_side, cudaStreamNonBlocking);
        cudaEventCreateWithFlags(&e_fork,  cudaEventDisableTiming);
        cudaEventCreateWithFlags(&e_build, cudaEventDisableTiming);
        cudaEventCreateWithFlags(&e_join,  cudaEventDisableTiming);
    }
    if (!attr_done) {
        cudaFuncSetAttribute(k_pool, cudaFuncAttributeMaxDynamicSharedMemorySize, 131072);
        attr_done = true;
    }

    // side stream: dense adjacency build, then adj-output memset
    cudaEventRecord(e_fork, 0);
    cudaStreamWaitEvent(s_side, e_fork, 0);
    k_buildA<<<NB, 256, 0, s_side>>>(esrc, edst);
    cudaEventRecord(e_build, s_side);
    cudaMemsetAsync(d_out, 0, (size_t)ADJ_ELEMS * sizeof(float), s_side);
    cudaEventRecord(e_join, s_side);

    // main stream
    k_prep<<<1280, 256>>>(h, Wf, Wp);
    k_gemm_mma<<<dim3(128, 4), 256>>>();
    cudaStreamWaitEvent(0, e_build, 0);
    k_prepAT<<<2048, 256>>>();
    k_agg2<<<dim3(NB, 2, 2), 256>>>();
    k_epi<<<1024, 256>>>(bf, bp);
    k_as2<<<dim3(NB, 2), 256>>>();
    cudaStreamWaitEvent(0, e_join, 0);
    k_pool<<<dim3(NB, 2), 512, 131072>>>(out);
}

// round 13
// speedup vs baseline: 1.1807x; 1.1798x over previous
#include <cuda_runtime.h>
#include <cuda_fp16.h>
#include <math.h>
#include <stdint.h>

#define NB   64
#define NPER 256
#define DIN  256
#define DOUT 128
#define EPER 8192
#define ADJ_N 8192
#define ADJ_ELEMS (67108864u)
#define NROWS (NB*NPER)          // 16384

// ---------------- scratch ----------------
__device__ float g_T[NROWS*512];          // X @ Wcat (cols: Wf_top|Wf_bot|Wp_top|Wp_bot)
__device__ float g_A[NB*NPER*NPER];       // dense adjacency counts (fp32)
__device__ float g_AG[NB*NPER*256];       // A @ [T_fbot|T_pbot]
__device__ float g_AS[NROWS*DOUT];        // A @ assign (fp32)
__device__ float g_ideg[NROWS];
// fp16x2 fragment arrays (uint32 words)
__device__ unsigned int g_Xf[NROWS*128];      // X      A-frag [mt][kc][lane][4]
__device__ unsigned int g_WTh[64*1024];       // Wcat^T B-frag hi [nt64][kc][lane][2]
__device__ unsigned int g_WTl[64*1024];       // lo
__device__ unsigned int g_Afrag[NB*16*2048];  // A (exact) A-frag [b][mt][kc][lane][4]
__device__ unsigned int g_Tf[NB*32768];       // T_bot  B-frag [b][nt32][kc][lane][2]
__device__ unsigned int g_Sf[NB*16384];       // assign B-frag [b][nt16][kc][lane][2]
__device__ unsigned int g_Ff[NB*16384];       // feat   B-frag
__device__ unsigned int g_ASf[NB*16384];      // AS     B-frag
__device__ unsigned int g_STf[NB*16384];      // S^T    A-frag [b][mt8][kc][lane][4]

// ---------------- mma.sync fp16 ----------
__device__ __forceinline__ void mma16816(float* c, const uint32_t* a, const uint32_t* b) {
    asm volatile(
        "mma.sync.aligned.m16n8k16.row.col.f32.f16.f16.f32 "
        "{%0,%1,%2,%3}, {%4,%5,%6,%7}, {%8,%9}, {%0,%1,%2,%3};"
        : "+f"(c[0]), "+f"(c[1]), "+f"(c[2]), "+f"(c[3])
        : "r"(a[0]), "r"(a[1]), "r"(a[2]), "r"(a[3]), "r"(b[0]), "r"(b[1]));
}

__device__ __forceinline__ unsigned int pack_h2(float a, float b) {
    __half2 p = __floats2half2_rn(a, b);
    return *reinterpret_cast<unsigned int*>(&p);
}
__device__ __forceinline__ void split_h2(float a, float b, unsigned int& hi, unsigned int& lo) {
    __half ah = __float2half_rn(a), bh = __float2half_rn(b);
    __half al = __float2half_rn(a - __half2float(ah));
    __half bl = __float2half_rn(b - __half2float(bh));
    __half2 h; h.x = ah; h.y = bh;
    __half2 l; l.x = al; l.y = bl;
    hi = *reinterpret_cast<unsigned int*>(&h);
    lo = *reinterpret_cast<unsigned int*>(&l);
}

// ---------------- K-buildA: dense adjacency + degrees ----------
__global__ void k_buildA(const int* __restrict__ esrc, const int* __restrict__ edst) {
    int b = blockIdx.x, t = threadIdx.x;
    float* A = g_A + (size_t)b*65536;
    float4* A4 = (float4*)A;
    for (int i = t; i < 16384; i += 256) A4[i] = make_float4(0.f, 0.f, 0.f, 0.f);
    __shared__ int scnt[NPER];
    if (t < 256) scnt[t] = 0;
    __syncthreads();
    const int* s = esrc + b*EPER;
    const int* d = edst + b*EPER;
    for (int e = t; e < EPER; e += 256) {
        int dst = d[e], src = s[e];
        atomicAdd(&scnt[dst], 1);
        atomicAdd(&A[dst*256 + src], 1.0f);
    }
    __syncthreads();
    if (t < 256) {
        int c = scnt[t];
        g_ideg[b*NPER + t] = 1.0f / (float)(c > 0 ? c : 1);
    }
}

// ---------------- K-prep: X single-fp16 A-frags; W split hi/lo B-frags --------
__global__ void __launch_bounds__(256) k_prep(
        const float* __restrict__ h,
        const float* __restrict__ Wf, const float* __restrict__ Wp) {
    __shared__ float hs[16*256];
    int t = threadIdx.x;
    if (blockIdx.x < 1024) {
        int mt = blockIdx.x;
        const float4* src = (const float4*)(h + (size_t)mt*16*DIN);
        #pragma unroll
        for (int k = 0; k < 4; k++)
            ((float4*)hs)[t + k*256] = src[t + k*256];
        __syncthreads();
        #pragma unroll
        for (int k = 0; k < 8; k++) {
            int w = t + k*256;
            int reg = w & 3, lane = (w >> 2) & 31, kc = w >> 7;
            int g = lane >> 2, tg = lane & 3;
            int row = g + (reg & 1)*8;
            int wc = tg + (reg >> 1)*4;
            const float* hp = hs + row*256 + (kc*8 + wc)*2;
            g_Xf[(size_t)mt*2048 + w] = pack_h2(hp[0], hp[1]);
        }
    } else {
        int widx = (blockIdx.x - 1024)*256 + t;   // [0, 65536)
        int reg = widx & 1, lane = (widx >> 1) & 31, kc = (widx >> 6) & 15, nt = widx >> 10;
        int g = lane >> 2, tg = lane & 3;
        int n = nt*8 + g;
        int w = tg + reg*4;
        int k = (kc*8 + w)*2;
        int seg = n >> 7;
        const float* Wb = (seg < 2) ? Wf : Wp;
        int col = n & 127;
        int krow = k + ((seg & 1) ? 256 : 0);
        float x0 = Wb[(size_t)krow*128 + col];
        float x1 = Wb[(size_t)(krow+1)*128 + col];
        unsigned int hi, lo;
        split_h2(x0, x1, hi, lo);
        g_WTh[widx] = hi;
        g_WTl[widx] = lo;
    }
}

// ---------------- K-gemm: T = X @ Wcat (2-pass: X*(Wh+Wl)) ----------------
__global__ void __launch_bounds__(256) k_gemm_mma() {
    int t = threadIdx.x, lane = t & 31, w = t >> 5;
    int wm = w & 1, wn = w >> 1;
    int mt0 = blockIdx.x*8 + wm*4;
    int nt0 = blockIdx.y*16 + wn*4;

    float acc[4][4][4];
    #pragma unroll
    for (int i = 0; i < 4; i++)
        #pragma unroll
        for (int j = 0; j < 4; j++)
            #pragma unroll
            for (int r = 0; r < 4; r++) acc[i][j][r] = 0.f;

    const uint4* X4 = (const uint4*)g_Xf;
    const uint2* Wh2 = (const uint2*)g_WTh;
    const uint2* Wl2 = (const uint2*)g_WTl;

    for (int kc = 0; kc < 16; kc++) {
        uint4 Af[4];
        uint2 Bh[4], Bl[4];
        #pragma unroll
        for (int i = 0; i < 4; i++)
            Af[i] = X4[((mt0 + i)*16 + kc)*32 + lane];
        #pragma unroll
        for (int j = 0; j < 4; j++) {
            int off = ((nt0 + j)*16 + kc)*32 + lane;
            Bh[j] = Wh2[off];
            Bl[j] = Wl2[off];
        }
        #pragma unroll
        for (int i = 0; i < 4; i++) {
            #pragma unroll
            for (int j = 0; j < 4; j++) {
                mma16816(acc[i][j], (const uint32_t*)&Af[i], (const uint32_t*)&Bh[j]);
                mma16816(acc[i][j], (const uint32_t*)&Af[i], (const uint32_t*)&Bl[j]);
            }
        }
    }

    int g = lane >> 2, tg = lane & 3;
    #pragma unroll
    for (int i = 0; i < 4; i++) {
        #pragma unroll
        for (int j = 0; j < 4; j++) {
            size_t row = (size_t)(mt0 + i)*16 + g;
            size_t col = (size_t)(nt0 + j)*8 + tg*2;
            *(float2*)(g_T + row*512 + col)       = make_float2(acc[i][j][0], acc[i][j][1]);
            *(float2*)(g_T + (row + 8)*512 + col) = make_float2(acc[i][j][2], acc[i][j][3]);
        }
    }
}

// ---------------- K-prepAT: A A-frags (exact fp16) + T_bot single B-frags -----
__global__ void __launch_bounds__(256) k_prepAT() {
    __shared__ float sm[16*256];
    int t = threadIdx.x;
    if (blockIdx.x < 1024) {
        int b = blockIdx.x >> 4, mt = blockIdx.x & 15;
        const float4* src = (const float4*)(g_A + ((size_t)b*256 + mt*16)*256);
        #pragma unroll
        for (int k = 0; k < 4; k++) ((float4*)sm)[t + k*256] = src[t + k*256];
        __syncthreads();
        #pragma unroll
        for (int k = 0; k < 8; k++) {
            int w = t + k*256;
            int reg = w & 3, lane = (w >> 2) & 31, kc = w >> 7;
            int g = lane >> 2, tg = lane & 3;
            int row = g + (reg & 1)*8;
            int col = kc*16 + tg*2 + (reg >> 1)*8;
            g_Afrag[(size_t)(b*16 + mt)*2048 + w] = pack_h2(sm[row*256 + col], sm[row*256 + col + 1]);
        }
    } else {
        int q = blockIdx.x - 1024;
        int b = q >> 4, kc = q & 15;
        #pragma unroll
        for (int k = 0; k < 4; k++) {
            int idx4 = t + k*256;
            int r = idx4 >> 6, cc4 = idx4 & 63;
            int tcol4 = (cc4 < 32) ? (32 + cc4) : (64 + cc4);
            ((float4*)sm)[idx4] =
                *(const float4*)(g_T + (size_t)(b*256 + kc*16 + r)*512 + tcol4*4);
        }
        __syncthreads();
        #pragma unroll
        for (int k = 0; k < 8; k++) {
            int w = t + k*256;   // 2048 words
            int reg = w & 1, lane = (w >> 1) & 31, nt = w >> 6;
            int g = lane >> 2, tg = lane & 3;
            int n = nt*8 + g;
            int k0 = tg*2 + reg*8;
            g_Tf[(size_t)b*32768 + nt*1024 + kc*64 + (w & 63)] =
                pack_h2(sm[k0*256 + n], sm[(k0+1)*256 + n]);
        }
    }
}

// ---------------- K-agg2: AG = A @ [T_fbot|T_pbot] (1-pass) --------------------
__global__ void __launch_bounds__(256) k_agg2() {
    int t = threadIdx.x, lane = t & 31, w = t >> 5;
    int b = blockIdx.x, mh = blockIdx.y, nh = blockIdx.z;
    int wm = w & 1, wn = w >> 1;
    int mt0 = mh*8 + wm*4;
    int nt0 = nh*16 + wn*4;

    float acc[4][4][4];
    #pragma unroll
    for (int i = 0; i < 4; i++)
        #pragma unroll
        for (int j = 0; j < 4; j++)
            #pragma unroll
            for (int r = 0; r < 4; r++) acc[i][j][r] = 0.f;

    const uint4* A4 = (const uint4*)g_Afrag;
    const uint2* B2 = (const uint2*)g_Tf;

    for (int kc = 0; kc < 16; kc++) {
        uint4 Af[4];
        uint2 Bf[4];
        #pragma unroll
        for (int i = 0; i < 4; i++)
            Af[i] = A4[(size_t)(b*16 + mt0 + i)*512 + kc*32 + lane];
        #pragma unroll
        for (int j = 0; j < 4; j++)
            Bf[j] = B2[(size_t)b*16384 + (nt0 + j)*512 + kc*32 + lane];
        #pragma unroll
        for (int i = 0; i < 4; i++)
            #pragma unroll
            for (int j = 0; j < 4; j++)
                mma16816(acc[i][j], (const uint32_t*)&Af[i], (const uint32_t*)&Bf[j]);
    }

    int g = lane >> 2, tg = lane & 3;
    #pragma unroll
    for (int i = 0; i < 4; i++) {
        #pragma unroll
        for (int j = 0; j < 4; j++) {
            size_t row = (size_t)(mt0 + i)*16 + g;
            size_t col = (size_t)(nt0 + j)*8 + tg*2;
            *(float2*)(g_AG + ((size_t)b*256 + row)*256 + col)     = make_float2(acc[i][j][0], acc[i][j][1]);
            *(float2*)(g_AG + ((size_t)b*256 + row + 8)*256 + col) = make_float2(acc[i][j][2], acc[i][j][3]);
        }
    }
}

// ---------------- K-epi: z -> norm/relu(/softmax); emit S,F,S^T fragments ------
// grid 1024 (b,kc); block 256 = 8 warps x 4 tasks (16 nodes x 2 which)
__global__ void __launch_bounds__(256) k_epi(const float* __restrict__ bf,
                                             const float* __restrict__ bp) {
    __shared__ float smF[16*128];
    __shared__ float smS[16*128];
    int b = blockIdx.x >> 4, kc = blockIdx.x & 15;
    int t = threadIdx.x, w = t >> 5, l = t & 31;

    #pragma unroll
    for (int i = 0; i < 4; i++) {
        int task = w*4 + i;
        int which = task >> 4, nl = task & 15;
        int gi = b*256 + kc*16 + nl;
        const float* bias = which ? bp : bf;
        float4 bias4 = *(const float4*)(bias + l*4);
        float4 top = *(const float4*)(g_T + (size_t)gi*512 + which*256 + l*4);
        float4 ag  = *(const float4*)(g_AG + (size_t)gi*256 + which*128 + l*4);
        float ideg = g_ideg[gi];

        float z0 = fmaf(ideg, ag.x, top.x) + bias4.x;
        float z1 = fmaf(ideg, ag.y, top.y) + bias4.y;
        float z2 = fmaf(ideg, ag.z, top.z) + bias4.z;
        float z3 = fmaf(ideg, ag.w, top.w) + bias4.w;

        float ss = z0*z0 + z1*z1 + z2*z2 + z3*z3;
        #pragma unroll
        for (int o = 16; o > 0; o >>= 1) ss += __shfl_xor_sync(0xffffffffu, ss, o);
        float inv = rsqrtf(fmaxf(ss, 1e-24f));
        z0 = fmaxf(z0*inv, 0.f); z1 = fmaxf(z1*inv, 0.f);
        z2 = fmaxf(z2*inv, 0.f); z3 = fmaxf(z3*inv, 0.f);

        if (which == 0) {
            smF[nl*128 + l*4 + 0] = z0;
            smF[nl*128 + l*4 + 1] = z1;
            smF[nl*128 + l*4 + 2] = z2;
            smF[nl*128 + l*4 + 3] = z3;
        } else {
            float m = fmaxf(fmaxf(z0, z1), fmaxf(z2, z3));
            #pragma unroll
            for (int o = 16; o > 0; o >>= 1) m = fmaxf(m, __shfl_xor_sync(0xffffffffu, m, o));
            float e0 = __expf(z0 - m), e1 = __expf(z1 - m);
            float e2 = __expf(z2 - m), e3 = __expf(z3 - m);
            float s = (e0 + e1) + (e2 + e3);
            #pragma unroll
            for (int o = 16; o > 0; o >>= 1) s += __shfl_xor_sync(0xffffffffu, s, o);
            float isum = 1.0f / s;
            smS[nl*128 + l*4 + 0] = e0*isum;
            smS[nl*128 + l*4 + 1] = e1*isum;
            smS[nl*128 + l*4 + 2] = e2*isum;
            smS[nl*128 + l*4 + 3] = e3*isum;
        }
    }
    __syncthreads();

    // B-frags for S and F (1024 words each, this (b,kc))
    #pragma unroll
    for (int k = 0; k < 4; k++) {
        int w2 = t + k*256;
        int reg = w2 & 1, lane = (w2 >> 1) & 31, nt = w2 >> 6;
        int g = lane >> 2, tg = lane & 3;
        int n = nt*8 + g;
        int k0 = tg*2 + reg*8;
        size_t idx = (size_t)b*16384 + nt*1024 + kc*64 + (w2 & 63);
        g_Sf[idx] = pack_h2(smS[k0*128 + n], smS[(k0+1)*128 + n]);
        g_Ff[idx] = pack_h2(smF[k0*128 + n], smF[(k0+1)*128 + n]);
    }
    // A-frags for S^T (1024 words)
    #pragma unroll
    for (int k = 0; k < 4; k++) {
        int w2 = t + k*256;
        int reg = w2 & 3, lane = (w2 >> 2) & 31, mt = w2 >> 7;
        int g = lane >> 2, tg = lane & 3;
        int m = mt*16 + g + (reg & 1)*8;
        int k0 = tg*2 + (reg >> 1)*8;
        g_STf[(size_t)b*16384 + mt*2048 + kc*128 + lane*4 + reg] =
            pack_h2(smS[k0*128 + m], smS[(k0+1)*128 + m]);
    }
}

// ---------------- K-as2: AS = A @ S (1-pass) -----------------------------------
__global__ void __launch_bounds__(256) k_as2() {
    int t = threadIdx.x, lane = t & 31, w = t >> 5;
    int b = blockIdx.x;
    int wm = w & 1, wn = w >> 1;
    int mt0 = blockIdx.y*8 + wm*4;
    int nt0 = wn*4;

    float acc[4][4][4];
    #pragma unroll
    for (int i = 0; i < 4; i++)
        #pragma unroll
        for (int j = 0; j < 4; j++)
            #pragma unroll
            for (int r = 0; r < 4; r++) acc[i][j][r] = 0.f;

    const uint4* A4 = (const uint4*)g_Afrag;
    const uint2* B2 = (const uint2*)g_Sf;

    for (int kc = 0; kc < 16; kc++) {
        uint4 Af[4];
        uint2 Bf[4];
        #pragma unroll
        for (int i = 0; i < 4; i++)
            Af[i] = A4[(size_t)(b*16 + mt0 + i)*512 + kc*32 + lane];
        #pragma unroll
        for (int j = 0; j < 4; j++)
            Bf[j] = B2[(size_t)b*8192 + (nt0 + j)*512 + kc*32 + lane];
        #pragma unroll
        for (int i = 0; i < 4; i++)
            #pragma unroll
            for (int j = 0; j < 4; j++)
                mma16816(acc[i][j], (const uint32_t*)&Af[i], (const uint32_t*)&Bf[j]);
    }

    int g = lane >> 2, tg = lane & 3;
    #pragma unroll
    for (int i = 0; i < 4; i++) {
        #pragma unroll
        for (int j = 0; j < 4; j++) {
            size_t row = (size_t)(mt0 + i)*16 + g;
            size_t col = (size_t)(nt0 + j)*8 + tg*2;
            *(float2*)(g_AS + ((size_t)b*256 + row)*128 + col)     = make_float2(acc[i][j][0], acc[i][j][1]);
            *(float2*)(g_AS + ((size_t)b*256 + row + 8)*128 + col) = make_float2(acc[i][j][2], acc[i][j][3]);
        }
    }
}

// ---------------- K-prepAS: AS fp32 -> B-frags ----------------------------------
__global__ void __launch_bounds__(256) k_prepAS() {
    __shared__ float sm[16*128];
    int b = blockIdx.x >> 4, kc = blockIdx.x & 15;
    int t = threadIdx.x;
    #pragma unroll
    for (int k = 0; k < 2; k++) {
        int i4 = t + k*256;  // 512 float4
        ((float4*)sm)[i4] = *(const float4*)(g_AS + ((size_t)b*256 + kc*16)*128 + i4*4);
    }
    __syncthreads();
    #pragma unroll
    for (int k = 0; k < 4; k++) {
        int w2 = t + k*256;
        int reg = w2 & 1, lane = (w2 >> 1) & 31, nt = w2 >> 6;
        int g = lane >> 2, tg = lane & 3;
        int n = nt*8 + g;
        int k0 = tg*2 + reg*8;
        g_ASf[(size_t)b*16384 + nt*1024 + kc*64 + (w2 & 63)] =
            pack_h2(sm[k0*128 + n], sm[(k0+1)*128 + n]);
    }
}

// ---------------- K-pool: D = S^T @ (F or AS) via HMMA (single pass) ----------
// grid (NB, 2 which); block 256 = 8 warps (wm2 x wn4); warp 4mt x 4nt x 16kc
// covers full 8mt (128 rows) x 16nt (128 cols).
__global__ void __launch_bounds__(256) k_pool_mma(float* __restrict__ out) {
    int t = threadIdx.x, lane = t & 31, w = t >> 5;
    int b = blockIdx.x, which = blockIdx.y;
    int wm = w & 1, wn = w >> 1;
    int mt0 = wm*4;      // 0 or 4  -> mt 0..7
    int nt0 = wn*4;      // 0,4,8,12 -> nt 0..15

    float acc[4][4][4];
    #pragma unroll
    for (int i = 0; i < 4; i++)
        #pragma unroll
        for (int j = 0; j < 4; j++)
            #pragma unroll
            for (int r = 0; r < 4; r++) acc[i][j][r] = 0.f;

    const uint4* A4 = (const uint4*)g_STf;
    const uint2* B2 = (const uint2*)(which ? g_ASf : g_Ff);

    for (int kc = 0; kc < 16; kc++) {
        uint4 Af[4];
        uint2 Bf[4];
        #pragma unroll
        for (int i = 0; i < 4; i++)
            Af[i] = A4[(size_t)b*4096 + (mt0 + i)*512 + kc*32 + lane];
        #pragma unroll
        for (int j = 0; j < 4; j++)
            Bf[j] = B2[(size_t)b*8192 + (nt0 + j)*512 + kc*32 + lane];
        #pragma unroll
        for (int i = 0; i < 4; i++)
            #pragma unroll
            for (int j = 0; j < 4; j++)
                mma16816(acc[i][j], (const uint32_t*)&Af[i], (const uint32_t*)&Bf[j]);
    }

    int g = lane >> 2, tg = lane & 3;
    #pragma unroll
    for (int i = 0; i < 4; i++) {
        #pragma unroll
        for (int j = 0; j < 4; j++) {
            size_t row = (size_t)(mt0 + i)*16 + g;          // 0..127
            size_t col = (size_t)(nt0 + j)*8 + tg*2;        // 0..127
            size_t grow = (size_t)b*128 + row;
            size_t base = which ? (grow*ADJ_N + (size_t)b*128 + col)
                                : ((size_t)ADJ_ELEMS + grow*DOUT + col);
            *(float2*)(out + base) = make_float2(acc[i][j][0], acc[i][j][1]);
            size_t grow2 = grow + 8;
            size_t base2 = which ? (grow2*ADJ_N + (size_t)b*128 + col)
                                 : ((size_t)ADJ_ELEMS + grow2*DOUT + col);
            *(float2*)(out + base2) = make_float2(acc[i][j][2], acc[i][j][3]);
        }
    }
}

// ---------------- launch ----------------
extern "C" void kernel_launch(void* const* d_in, const int* in_sizes, int n_in,
                              void* d_out, int out_size) {
    const float* h    = (const float*)d_in[0];
    const int*   esrc = (const int*)d_in[1];
    const int*   edst = (const int*)d_in[2];
    const float* Wf   = (const float*)d_in[3];
    const float* bf   = (const float*)d_in[4];
    const float* Wp   = (const float*)d_in[5];
    const float* bp   = (const float*)d_in[6];
    float* out = (float*)d_out;

    static cudaStream_t s_side = nullptr;
    static cudaEvent_t  e_fork = nullptr, e_build = nullptr, e_join = nullptr;
    if (!s_side) {
        cudaStreamCreateWithFlags(&s_side, cudaStreamNonBlocking);
        cudaEventCreateWithFlags(&e_fork,  cudaEventDisableTiming);
        cudaEventCreateWithFlags(&e_build, cudaEventDisableTiming);
        cudaEventCreateWithFlags(&e_join,  cudaEventDisableTiming);
    }

    // side stream: dense adjacency build, then adj-output memset
    cudaEventRecord(e_fork, 0);
    cudaStreamWaitEvent(s_side, e_fork, 0);
    k_buildA<<<NB, 256, 0, s_side>>>(esrc, edst);
    cudaEventRecord(e_build, s_side);
    cudaMemsetAsync(d_out, 0, (size_t)ADJ_ELEMS * sizeof(float), s_side);
    cudaEventRecord(e_join, s_side);

    // main stream
    k_prep<<<1280, 256>>>(h, Wf, Wp);
    k_gemm_mma<<<dim3(128, 4), 256>>>();
    cudaStreamWaitEvent(0, e_build, 0);
    k_prepAT<<<2048, 256>>>();
    k_agg2<<<dim3(NB, 2, 2), 256>>>();
    k_epi<<<1024, 256>>>(bf, bp);
    k_as2<<<dim3(NB, 2), 256>>>();
    k_prepAS<<<1024, 256>>>();
    cudaStreamWaitEvent(0, e_join, 0);
    k_pool_mma<<<dim3(NB, 2), 256>>>(out);
}

// round 14
// speedup vs baseline: 1.2452x; 1.0546x over previous
#include <cuda_runtime.h>
#include <cuda_fp16.h>
#include <math.h>
#include <stdint.h>

#define NB   64
#define NPER 256
#define DIN  256
#define DOUT 128
#define EPER 8192
#define ADJ_N 8192
#define ADJ_ELEMS (67108864u)
#define NROWS (NB*NPER)          // 16384

// ---------------- scratch ----------------
__device__ float g_T[NROWS*512];          // only cols 0..127 (f_top) and 256..383 (p_top) used
__device__ float g_A[NB*NPER*NPER];       // dense adjacency counts (fp32)
__device__ float g_AG[NB*NPER*256];       // A @ [T_fbot|T_pbot]
__device__ float g_ideg[NROWS];
// fp16x2 fragment arrays (uint32 words)
__device__ unsigned int g_Xf[NROWS*128];      // X      A-frag [mt][kc][lane][4]
__device__ unsigned int g_WTf[64*1024];       // Wcat^T B-frag [nt64][kc][lane][2]
__device__ unsigned int g_Afrag[NB*16*2048];  // A (exact) A-frag [b][mt][kc][lane][4]
__device__ unsigned int g_Tf[NB*32768];       // T_bot  B-frag [b][nt32][kc][lane][2]
__device__ unsigned int g_Sf[NB*16384];       // assign B-frag [b][nt16][kc][lane][2]
__device__ unsigned int g_Ff[NB*16384];       // feat   B-frag
__device__ unsigned int g_ASf[NB*16384];      // AS     B-frag
__device__ unsigned int g_STf[NB*16384];      // S^T    A-frag [b][mt8][kc][lane][4]

// ---------------- mma.sync fp16 ----------
__device__ __forceinline__ void mma16816(float* c, const uint32_t* a, const uint32_t* b) {
    asm volatile(
        "mma.sync.aligned.m16n8k16.row.col.f32.f16.f16.f32 "
        "{%0,%1,%2,%3}, {%4,%5,%6,%7}, {%8,%9}, {%0,%1,%2,%3};"
        : "+f"(c[0]), "+f"(c[1]), "+f"(c[2]), "+f"(c[3])
        : "r"(a[0]), "r"(a[1]), "r"(a[2]), "r"(a[3]), "r"(b[0]), "r"(b[1]));
}

__device__ __forceinline__ unsigned int pack_h2(float a, float b) {
    __half2 p = __floats2half2_rn(a, b);
    return *reinterpret_cast<unsigned int*>(&p);
}

// ---------------- K-buildA: dense adjacency + degrees ----------
__global__ void k_buildA(const int* __restrict__ esrc, const int* __restrict__ edst) {
    int b = blockIdx.x, t = threadIdx.x;
    float* A = g_A + (size_t)b*65536;
    float4* A4 = (float4*)A;
    for (int i = t; i < 16384; i += 256) A4[i] = make_float4(0.f, 0.f, 0.f, 0.f);
    __shared__ int scnt[NPER];
    if (t < 256) scnt[t] = 0;
    __syncthreads();
    const int* s = esrc + b*EPER;
    const int* d = edst + b*EPER;
    for (int e = t; e < EPER; e += 256) {
        int dst = d[e], src = s[e];
        atomicAdd(&scnt[dst], 1);
        atomicAdd(&A[dst*256 + src], 1.0f);
    }
    __syncthreads();
    if (t < 256) {
        int c = scnt[t];
        g_ideg[b*NPER + t] = 1.0f / (float)(c > 0 ? c : 1);
    }
}

// ---------------- K-prep: X A-frags; W B-frags (single fp16) --------
__global__ void __launch_bounds__(256) k_prep(
        const float* __restrict__ h,
        const float* __restrict__ Wf, const float* __restrict__ Wp) {
    __shared__ float hs[16*256];
    int t = threadIdx.x;
    if (blockIdx.x < 1024) {
        int mt = blockIdx.x;
        const float4* src = (const float4*)(h + (size_t)mt*16*DIN);
        #pragma unroll
        for (int k = 0; k < 4; k++)
            ((float4*)hs)[t + k*256] = src[t + k*256];
        __syncthreads();
        #pragma unroll
        for (int k = 0; k < 8; k++) {
            int w = t + k*256;
            int reg = w & 3, lane = (w >> 2) & 31, kc = w >> 7;
            int g = lane >> 2, tg = lane & 3;
            int row = g + (reg & 1)*8;
            int wc = tg + (reg >> 1)*4;
            const float* hp = hs + row*256 + (kc*8 + wc)*2;
            g_Xf[(size_t)mt*2048 + w] = pack_h2(hp[0], hp[1]);
        }
    } else {
        int widx = (blockIdx.x - 1024)*256 + t;   // [0, 65536)
        int reg = widx & 1, lane = (widx >> 1) & 31, kc = (widx >> 6) & 15, nt = widx >> 10;
        int g = lane >> 2, tg = lane & 3;
        int n = nt*8 + g;
        int w = tg + reg*4;
        int k = (kc*8 + w)*2;
        int seg = n >> 7;
        const float* Wb = (seg < 2) ? Wf : Wp;
        int col = n & 127;
        int krow = k + ((seg & 1) ? 256 : 0);
        float x0 = Wb[(size_t)krow*128 + col];
        float x1 = Wb[(size_t)(krow+1)*128 + col];
        g_WTf[widx] = pack_h2(x0, x1);
    }
}

// ---------------- K-gemm: T = X @ Wcat (1-pass fp16) ----------------
// grid (128, 4); y in {0,2}: write fp32 T (top halves); y in {1,3}: emit Tf frags.
__global__ void __launch_bounds__(256) k_gemm_mma() {
    extern __shared__ float smT[];      // 128 x 128 staging (64KB) for frag emission
    int t = threadIdx.x, lane = t & 31, w = t >> 5;
    int wm = w & 1, wn = w >> 1;
    int mt0 = blockIdx.x*8 + wm*4;
    int nt0 = blockIdx.y*16 + wn*4;

    float acc[4][4][4];
    #pragma unroll
    for (int i = 0; i < 4; i++)
        #pragma unroll
        for (int j = 0; j < 4; j++)
            #pragma unroll
            for (int r = 0; r < 4; r++) acc[i][j][r] = 0.f;

    const uint4* X4 = (const uint4*)g_Xf;
    const uint2* W2 = (const uint2*)g_WTf;

    for (int kc = 0; kc < 16; kc++) {
        uint4 Af[4];
        uint2 Bf[4];
        #pragma unroll
        for (int i = 0; i < 4; i++)
            Af[i] = X4[((mt0 + i)*16 + kc)*32 + lane];
        #pragma unroll
        for (int j = 0; j < 4; j++)
            Bf[j] = W2[((nt0 + j)*16 + kc)*32 + lane];
        #pragma unroll
        for (int i = 0; i < 4; i++)
            #pragma unroll
            for (int j = 0; j < 4; j++)
                mma16816(acc[i][j], (const uint32_t*)&Af[i], (const uint32_t*)&Bf[j]);
    }

    int g = lane >> 2, tg = lane & 3;
    if ((blockIdx.y & 1) == 0) {
        // top halves: direct fp32 store to g_T
        #pragma unroll
        for (int i = 0; i < 4; i++) {
            #pragma unroll
            for (int j = 0; j < 4; j++) {
                size_t row = (size_t)(mt0 + i)*16 + g;
                size_t col = (size_t)(nt0 + j)*8 + tg*2;
                *(float2*)(g_T + row*512 + col)       = make_float2(acc[i][j][0], acc[i][j][1]);
                *(float2*)(g_T + (row + 8)*512 + col) = make_float2(acc[i][j][2], acc[i][j][3]);
            }
        }
    } else {
        // bottom halves: stage in smem, emit fp16 B-frags (Tf)
        #pragma unroll
        for (int i = 0; i < 4; i++) {
            #pragma unroll
            for (int j = 0; j < 4; j++) {
                int row = (wm*4 + i)*16 + g;                     // 0..127 within block
                int col = (wn*4 + j)*8 + tg*2;                   // 0..127 within tile
                *(float2*)(smT + row*128 + col)       = make_float2(acc[i][j][0], acc[i][j][1]);
                *(float2*)(smT + (row + 8)*128 + col) = make_float2(acc[i][j][2], acc[i][j][3]);
            }
        }
        __syncthreads();
        int b = blockIdx.x >> 1, half = blockIdx.x & 1;
        int ntbase = (blockIdx.y == 1) ? 0 : 16;
        #pragma unroll
        for (int k = 0; k < 32; k++) {
            int w2 = t + k*256;               // [0, 8192)
            int reg = w2 & 1, ln = (w2 >> 1) & 31, ntl = (w2 >> 6) & 15, kcl = w2 >> 10;
            int gg = ln >> 2, tt = ln & 3;
            int n = ntl*8 + gg;
            int k0 = tt*2 + reg*8;
            int row = kcl*16 + k0;
            g_Tf[(size_t)b*32768 + (ntbase + ntl)*1024 + (half*8 + kcl)*64 + ln*2 + reg] =
                pack_h2(smT[row*128 + n], smT[(row + 1)*128 + n]);
        }
    }
}

// ---------------- K-prepA: A -> exact fp16 A-frags ----------
__global__ void __launch_bounds__(256) k_prepA() {
    __shared__ float sm[16*256];
    int t = threadIdx.x;
    int b = blockIdx.x >> 4, mt = blockIdx.x & 15;
    const float4* src = (const float4*)(g_A + ((size_t)b*256 + mt*16)*256);
    #pragma unroll
    for (int k = 0; k < 4; k++) ((float4*)sm)[t + k*256] = src[t + k*256];
    __syncthreads();
    #pragma unroll
    for (int k = 0; k < 8; k++) {
        int w = t + k*256;
        int reg = w & 3, lane = (w >> 2) & 31, kc = w >> 7;
        int g = lane >> 2, tg = lane & 3;
        int row = g + (reg & 1)*8;
        int col = kc*16 + tg*2 + (reg >> 1)*8;
        g_Afrag[(size_t)(b*16 + mt)*2048 + w] = pack_h2(sm[row*256 + col], sm[row*256 + col + 1]);
    }
}

// ---------------- K-agg2: AG = A @ [T_fbot|T_pbot] (1-pass) --------------------
__global__ void __launch_bounds__(256) k_agg2() {
    int t = threadIdx.x, lane = t & 31, w = t >> 5;
    int b = blockIdx.x, mh = blockIdx.y, nh = blockIdx.z;
    int wm = w & 1, wn = w >> 1;
    int mt0 = mh*8 + wm*4;
    int nt0 = nh*16 + wn*4;

    float acc[4][4][4];
    #pragma unroll
    for (int i = 0; i < 4; i++)
        #pragma unroll
        for (int j = 0; j < 4; j++)
            #pragma unroll
            for (int r = 0; r < 4; r++) acc[i][j][r] = 0.f;

    const uint4* A4 = (const uint4*)g_Afrag;
    const uint2* B2 = (const uint2*)g_Tf;

    for (int kc = 0; kc < 16; kc++) {
        uint4 Af[4];
        uint2 Bf[4];
        #pragma unroll
        for (int i = 0; i < 4; i++)
            Af[i] = A4[(size_t)(b*16 + mt0 + i)*512 + kc*32 + lane];
        #pragma unroll
        for (int j = 0; j < 4; j++)
            Bf[j] = B2[(size_t)b*16384 + (nt0 + j)*512 + kc*32 + lane];
        #pragma unroll
        for (int i = 0; i < 4; i++)
            #pragma unroll
            for (int j = 0; j < 4; j++)
                mma16816(acc[i][j], (const uint32_t*)&Af[i], (const uint32_t*)&Bf[j]);
    }

    int g = lane >> 2, tg = lane & 3;
    #pragma unroll
    for (int i = 0; i < 4; i++) {
        #pragma unroll
        for (int j = 0; j < 4; j++) {
            size_t row = (size_t)(mt0 + i)*16 + g;
            size_t col = (size_t)(nt0 + j)*8 + tg*2;
            *(float2*)(g_AG + ((size_t)b*256 + row)*256 + col)     = make_float2(acc[i][j][0], acc[i][j][1]);
            *(float2*)(g_AG + ((size_t)b*256 + row + 8)*256 + col) = make_float2(acc[i][j][2], acc[i][j][3]);
        }
    }
}

// ---------------- K-epi: z -> norm/relu(/softmax); emit S,F,S^T fragments ------
__global__ void __launch_bounds__(256) k_epi(const float* __restrict__ bf,
                                             const float* __restrict__ bp) {
    __shared__ float smF[16*128];
    __shared__ float smS[16*128];
    int b = blockIdx.x >> 4, kc = blockIdx.x & 15;
    int t = threadIdx.x, w = t >> 5, l = t & 31;

    #pragma unroll
    for (int i = 0; i < 4; i++) {
        int task = w*4 + i;
        int which = task >> 4, nl = task & 15;
        int gi = b*256 + kc*16 + nl;
        const float* bias = which ? bp : bf;
        float4 bias4 = *(const float4*)(bias + l*4);
        float4 top = *(const float4*)(g_T + (size_t)gi*512 + which*256 + l*4);
        float4 ag  = *(const float4*)(g_AG + (size_t)gi*256 + which*128 + l*4);
        float ideg = g_ideg[gi];

        float z0 = fmaf(ideg, ag.x, top.x) + bias4.x;
        float z1 = fmaf(ideg, ag.y, top.y) + bias4.y;
        float z2 = fmaf(ideg, ag.z, top.z) + bias4.z;
        float z3 = fmaf(ideg, ag.w, top.w) + bias4.w;

        float ss = z0*z0 + z1*z1 + z2*z2 + z3*z3;
        #pragma unroll
        for (int o = 16; o > 0; o >>= 1) ss += __shfl_xor_sync(0xffffffffu, ss, o);
        float inv = rsqrtf(fmaxf(ss, 1e-24f));
        z0 = fmaxf(z0*inv, 0.f); z1 = fmaxf(z1*inv, 0.f);
        z2 = fmaxf(z2*inv, 0.f); z3 = fmaxf(z3*inv, 0.f);

        if (which == 0) {
            smF[nl*128 + l*4 + 0] = z0;
            smF[nl*128 + l*4 + 1] = z1;
            smF[nl*128 + l*4 + 2] = z2;
            smF[nl*128 + l*4 + 3] = z3;
        } else {
            float m = fmaxf(fmaxf(z0, z1), fmaxf(z2, z3));
            #pragma unroll
            for (int o = 16; o > 0; o >>= 1) m = fmaxf(m, __shfl_xor_sync(0xffffffffu, m, o));
            float e0 = __expf(z0 - m), e1 = __expf(z1 - m);
            float e2 = __expf(z2 - m), e3 = __expf(z3 - m);
            float s = (e0 + e1) + (e2 + e3);
            #pragma unroll
            for (int o = 16; o > 0; o >>= 1) s += __shfl_xor_sync(0xffffffffu, s, o);
            float isum = 1.0f / s;
            smS[nl*128 + l*4 + 0] = e0*isum;
            smS[nl*128 + l*4 + 1] = e1*isum;
            smS[nl*128 + l*4 + 2] = e2*isum;
            smS[nl*128 + l*4 + 3] = e3*isum;
        }
    }
    __syncthreads();

    #pragma unroll
    for (int k = 0; k < 4; k++) {
        int w2 = t + k*256;
        int reg = w2 & 1, lane = (w2 >> 1) & 31, nt = w2 >> 6;
        int g = lane >> 2, tg = lane & 3;
        int n = nt*8 + g;
        int k0 = tg*2 + reg*8;
        size_t idx = (size_t)b*16384 + nt*1024 + kc*64 + (w2 & 63);
        g_Sf[idx] = pack_h2(smS[k0*128 + n], smS[(k0+1)*128 + n]);
        g_Ff[idx] = pack_h2(smF[k0*128 + n], smF[(k0+1)*128 + n]);
    }
    #pragma unroll
    for (int k = 0; k < 4; k++) {
        int w2 = t + k*256;
        int reg = w2 & 3, lane = (w2 >> 2) & 31, mt = w2 >> 7;
        int g = lane >> 2, tg = lane & 3;
        int m = mt*16 + g + (reg & 1)*8;
        int k0 = tg*2 + (reg >> 1)*8;
        g_STf[(size_t)b*16384 + mt*2048 + kc*128 + lane*4 + reg] =
            pack_h2(smS[k0*128 + m], smS[(k0+1)*128 + m]);
    }
}

// ---------------- K-as2: AS = A @ S (1-pass) -> emit ASf frags directly --------
// grid (NB, 2 mh); block 256; smem 64KB staging
__global__ void __launch_bounds__(256) k_as2() {
    extern __shared__ float smT[];      // 128 x 128
    int t = threadIdx.x, lane = t & 31, w = t >> 5;
    int b = blockIdx.x, mh = blockIdx.y;
    int wm = w & 1, wn = w >> 1;
    int mt0 = mh*8 + wm*4;
    int nt0 = wn*4;

    float acc[4][4][4];
    #pragma unroll
    for (int i = 0; i < 4; i++)
        #pragma unroll
        for (int j = 0; j < 4; j++)
            #pragma unroll
            for (int r = 0; r < 4; r++) acc[i][j][r] = 0.f;

    const uint4* A4 = (const uint4*)g_Afrag;
    const uint2* B2 = (const uint2*)g_Sf;

    for (int kc = 0; kc < 16; kc++) {
        uint4 Af[4];
        uint2 Bf[4];
        #pragma unroll
        for (int i = 0; i < 4; i++)
            Af[i] = A4[(size_t)(b*16 + mt0 + i)*512 + kc*32 + lane];
        #pragma unroll
        for (int j = 0; j < 4; j++)
            Bf[j] = B2[(size_t)b*8192 + (nt0 + j)*512 + kc*32 + lane];
        #pragma unroll
        for (int i = 0; i < 4; i++)
            #pragma unroll
            for (int j = 0; j < 4; j++)
                mma16816(acc[i][j], (const uint32_t*)&Af[i], (const uint32_t*)&Bf[j]);
    }

    int g = lane >> 2, tg = lane & 3;
    #pragma unroll
    for (int i = 0; i < 4; i++) {
        #pragma unroll
        for (int j = 0; j < 4; j++) {
            int row = (wm*4 + i)*16 + g;          // 0..127 within block
            int col = (wn*4 + j)*8 + tg*2;        // 0..127
            *(float2*)(smT + row*128 + col)       = make_float2(acc[i][j][0], acc[i][j][1]);
            *(float2*)(smT + (row + 8)*128 + col) = make_float2(acc[i][j][2], acc[i][j][3]);
        }
    }
    __syncthreads();
    #pragma unroll
    for (int k = 0; k < 32; k++) {
        int w2 = t + k*256;               // [0, 8192)
        int reg = w2 & 1, ln = (w2 >> 1) & 31, ntl = (w2 >> 6) & 15, kcl = w2 >> 10;
        int gg = ln >> 2, tt = ln & 3;
        int n = ntl*8 + gg;
        int k0 = tt*2 + reg*8;
        int row = kcl*16 + k0;
        g_ASf[(size_t)b*16384 + ntl*1024 + (mh*8 + kcl)*64 + ln*2 + reg] =
            pack_h2(smT[row*128 + n], smT[(row + 1)*128 + n]);
    }
}

// ---------------- K-pool: D = S^T @ (F or AS) via HMMA ----------
__global__ void __launch_bounds__(256) k_pool_mma(float* __restrict__ out) {
    int t = threadIdx.x, lane = t & 31, w = t >> 5;
    int b = blockIdx.x, which = blockIdx.y;
    int wm = w & 1, wn = w >> 1;
    int mt0 = wm*4;
    int nt0 = wn*4;

    float acc[4][4][4];
    #pragma unroll
    for (int i = 0; i < 4; i++)
        #pragma unroll
        for (int j = 0; j < 4; j++)
            #pragma unroll
            for (int r = 0; r < 4; r++) acc[i][j][r] = 0.f;

    const uint4* A4 = (const uint4*)g_STf;
    const uint2* B2 = (const uint2*)(which ? g_ASf : g_Ff);

    for (int kc = 0; kc < 16; kc++) {
        uint4 Af[4];
        uint2 Bf[4];
        #pragma unroll
        for (int i = 0; i < 4; i++)
            Af[i] = A4[(size_t)b*4096 + (mt0 + i)*512 + kc*32 + lane];
        #pragma unroll
        for (int j = 0; j < 4; j++)
            Bf[j] = B2[(size_t)b*8192 + (nt0 + j)*512 + kc*32 + lane];
        #pragma unroll
        for (int i = 0; i < 4; i++)
            #pragma unroll
            for (int j = 0; j < 4; j++)
                mma16816(acc[i][j], (const uint32_t*)&Af[i], (const uint32_t*)&Bf[j]);
    }

    int g = lane >> 2, tg = lane & 3;
    #pragma unroll
    for (int i = 0; i < 4; i++) {
        #pragma unroll
        for (int j = 0; j < 4; j++) {
            size_t row = (size_t)(mt0 + i)*16 + g;
            size_t col = (size_t)(nt0 + j)*8 + tg*2;
            size_t grow = (size_t)b*128 + row;
            size_t base = which ? (grow*ADJ_N + (size_t)b*128 + col)
                                : ((size_t)ADJ_ELEMS + grow*DOUT + col);
            *(float2*)(out + base) = make_float2(acc[i][j][0], acc[i][j][1]);
            size_t grow2 = grow + 8;
            size_t base2 = which ? (grow2*ADJ_N + (size_t)b*128 + col)
                                 : ((size_t)ADJ_ELEMS + grow2*DOUT + col);
            *(float2*)(out + base2) = make_float2(acc[i][j][2], acc[i][j][3]);
        }
    }
}

// ---------------- launch ----------------
extern "C" void kernel_launch(void* const* d_in, const int* in_sizes, int n_in,
                              void* d_out, int out_size) {
    const float* h    = (const float*)d_in[0];
    const int*   esrc = (const int*)d_in[1];
    const int*   edst = (const int*)d_in[2];
    const float* Wf   = (const float*)d_in[3];
    const float* bf   = (const float*)d_in[4];
    const float* Wp   = (const float*)d_in[5];
    const float* bp   = (const float*)d_in[6];
    float* out = (float*)d_out;

    static cudaStream_t s_side = nullptr;
    static cudaEvent_t  e_fork = nullptr, e_build = nullptr, e_join = nullptr;
    static bool attr_done = false;
    if (!s_side) {
        cudaStreamCreateWithFlags(&s_side, cudaStreamNonBlocking);
        cudaEventCreateWithFlags(&e_fork,  cudaEventDisableTiming);
        cudaEventCreateWithFlags(&e_build, cudaEventDisableTiming);
        cudaEventCreateWithFlags(&e_join,  cudaEventDisableTiming);
    }
    if (!attr_done) {
        cudaFuncSetAttribute(k_gemm_mma, cudaFuncAttributeMaxDynamicSharedMemorySize, 65536);
        cudaFuncSetAttribute(k_as2,      cudaFuncAttributeMaxDynamicSharedMemorySize, 65536);
        attr_done = true;
    }

    // side stream: dense adjacency build, then adj-output memset
    cudaEventRecord(e_fork, 0);
    cudaStreamWaitEvent(s_side, e_fork, 0);
    k_buildA<<<NB, 256, 0, s_side>>>(esrc, edst);
    cudaEventRecord(e_build, s_side);
    cudaMemsetAsync(d_out, 0, (size_t)ADJ_ELEMS * sizeof(float), s_side);
    cudaEventRecord(e_join, s_side);

    // main stream
    k_prep<<<1280, 256>>>(h, Wf, Wp);
    k_gemm_mma<<<dim3(128, 4), 256, 65536>>>();
    cudaStreamWaitEvent(0, e_build, 0);
    k_prepA<<<1024, 256>>>();
    k_agg2<<<dim3(NB, 2, 2), 256>>>();
    k_epi<<<1024, 256>>>(bf, bp);
    k_as2<<<dim3(NB, 2), 256, 65536>>>();
    cudaStreamWaitEvent(0, e_join, 0);
    k_pool_mma<<<dim3(NB, 2), 256>>>(out);
}